// round 8
// baseline (speedup 1.0000x reference)
#include <cuda_runtime.h>
#include <cuda_fp16.h>
#include <stdint.h>
#include <math.h>

#define N_NODES 100000
#define N_EDGES 1600000
#define CAP 96

// ---------------- static device scratch ----------------
__device__ __half g_y16[(size_t)N_NODES * 128];
__device__ __half g_h16[(size_t)N_NODES * 128];
__device__ __half g_w0h[128 * 128];
__device__ __half g_w1h[128 * 128];
__device__ __half g_w2h[128 * 64];
__device__ int   g_csr[(size_t)N_NODES * CAP];
__device__ int   g_cnt[N_NODES];
__device__ int   g_outdeg[N_NODES];
__device__ float g_nsrc[N_NODES];
__device__ float g_ndst[N_NODES];

// ---------------- graph build ----------------
__global__ void zero_kernel() {
    int i = blockIdx.x * blockDim.x + threadIdx.x;
    if (i < N_NODES) { g_cnt[i] = 0; g_outdeg[i] = 0; }
}

__global__ void build_kernel(const int* __restrict__ src, const int* __restrict__ dst) {
    int e = blockIdx.x * blockDim.x + threadIdx.x;
    if (e >= N_EDGES) return;
    int s = src[e];
    int d = dst[e];
    atomicAdd(&g_outdeg[s], 1);
    int pos = atomicAdd(&g_cnt[d], 1);
    if (pos < CAP) g_csr[(size_t)d * CAP + pos] = s;
}

__global__ void norm_kernel() {
    int i = blockIdx.x * blockDim.x + threadIdx.x;
    if (i >= N_NODES) return;
    int od = g_outdeg[i]; if (od < 1) od = 1;
    int id = g_cnt[i];    if (id < 1) id = 1;
    g_nsrc[i] = rsqrtf((float)od);
    g_ndst[i] = rsqrtf((float)id);
}

// ---------------- all three weight matrices fp32->fp16, one launch ----------------
__global__ void cvtw_kernel(const float* __restrict__ W0, const float* __restrict__ W1,
                            const float* __restrict__ W2,
                            __half* __restrict__ w0h, __half* __restrict__ w1h,
                            __half* __restrict__ w2h) {
    int i = blockIdx.x * blockDim.x + threadIdx.x;   // slot of 4 floats
    const float* src;
    __half* dst;
    int base;
    if (i < 4096)        { src = W0; dst = w0h; base = i; }
    else if (i < 8192)   { src = W1; dst = w1h; base = i - 4096; }
    else if (i < 10240)  { src = W2; dst = w2h; base = i - 8192; }
    else return;
    float4 v = ((const float4*)src)[base];
    __half2 lo = __floats2half2_rn(v.x, v.y);
    __half2 hi = __floats2half2_rn(v.z, v.w);
    uint2 o;
    o.x = *(uint32_t*)&lo;
    o.y = *(uint32_t*)&hi;
    ((uint2*)dst)[base] = o;
}

// ---------------- tensor-core helpers ----------------
// NOTE: inline-PTX bracket lists written with spaces to avoid template digraphs.
__device__ __forceinline__ uint32_t s2u(const void* p) {
    uint32_t a;
    asm("{ .reg .u64 t; cvta.to.shared.u64 t, %1; cvt.u32.u64 %0, t; }" : "=r"(a) : "l"(p));
    return a;
}

__device__ __forceinline__ void ldsm_x4(uint32_t& r0, uint32_t& r1, uint32_t& r2, uint32_t& r3,
                                        uint32_t addr) {
    asm volatile("ldmatrix.sync.aligned.m8n8.x4.shared.b16 { %0, %1, %2, %3 }, [ %4 ];"
                 : "=r"(r0), "=r"(r1), "=r"(r2), "=r"(r3) : "r"(addr));
}

__device__ __forceinline__ void ldsm_x4_t(uint32_t& r0, uint32_t& r1, uint32_t& r2, uint32_t& r3,
                                          uint32_t addr) {
    asm volatile("ldmatrix.sync.aligned.m8n8.x4.trans.shared.b16 { %0, %1, %2, %3 }, [ %4 ];"
                 : "=r"(r0), "=r"(r1), "=r"(r2), "=r"(r3) : "r"(addr));
}

__device__ __forceinline__ void mma_16816(float* c, const uint32_t* a, const uint32_t* b) {
    asm volatile(
        "mma.sync.aligned.m16n8k16.row.col.f32.f16.f16.f32 "
        "{ %0, %1, %2, %3 }, { %4, %5, %6, %7 }, { %8, %9 }, { %0, %1, %2, %3 };"
        : "+f"(c[0]), "+f"(c[1]), "+f"(c[2]), "+f"(c[3])
        : "r"(a[0]), "r"(a[1]), "r"(a[2]), "r"(a[3]), "r"(b[0]), "r"(b[1]));
}

// ---------------- HGEMM: Y[m,0:BN] = half( A[m,:] @ W[:,0:BN] ), K=128 ----
// No nsrc scaling here (moved to aggregation) so layer-1 GEMM has no
// dependency on the graph-build chain and can run concurrently with it.
template <int BN, bool F32IN>
__global__ __launch_bounds__(256) void hgemm_kernel(const float* __restrict__ Af,
                                                    const __half* __restrict__ Ah,
                                                    const __half* __restrict__ W,
                                                    __half* __restrict__ Y) {
    extern __shared__ __align__(16) char dynbuf[];
    const int LDA = 136;
    const int LDB = BN + 8;
    __half* As = (__half*)dynbuf;               // [128][136]
    __half* Bs = (__half*)dynbuf + 128 * LDA;   // [128][LDB]

    const int tid = threadIdx.x;
    const int m0  = blockIdx.x * 128;

    // load A tile (row-major [m][k]); zero-fill OOB rows; fp32 path converts inline
    {
#pragma unroll
        for (int i = 0; i < 8; i++) {
            int slot = tid + i * 256;            // 2048 slots of 8 halves
            int row = slot >> 4;
            int col = (slot & 15) * 8;
            int gr = m0 + row;
            uint4 v = make_uint4(0u, 0u, 0u, 0u);
            if (gr < N_NODES) {
                if (F32IN) {
                    float4 lo = *(const float4*)(Af + (size_t)gr * 128 + col);
                    float4 hi = *(const float4*)(Af + (size_t)gr * 128 + col + 4);
                    __half2 h0 = __floats2half2_rn(lo.x, lo.y);
                    __half2 h1 = __floats2half2_rn(lo.z, lo.w);
                    __half2 h2 = __floats2half2_rn(hi.x, hi.y);
                    __half2 h3 = __floats2half2_rn(hi.z, hi.w);
                    v.x = *(uint32_t*)&h0; v.y = *(uint32_t*)&h1;
                    v.z = *(uint32_t*)&h2; v.w = *(uint32_t*)&h3;
                } else {
                    v = *(const uint4*)(Ah + (size_t)gr * 128 + col);
                }
            }
            *(uint4*)(As + row * LDA + col) = v;
        }
    }
    // load B tile (row-major [k][n])
    {
        const int SLOTS = 128 * BN / 8;
#pragma unroll
        for (int i = 0; i < SLOTS / 256; i++) {
            int slot = tid + i * 256;
            int row = slot / (BN / 8);
            int col = (slot % (BN / 8)) * 8;
            *(uint4*)(Bs + row * LDB + col) = *(const uint4*)(W + (size_t)row * BN + col);
        }
    }
    __syncthreads();

    const int w = tid >> 5;
    const int lane = tid & 31;
    const int WN = (BN == 128) ? 32 : 16;
    const int NF = WN / 8;
    const int wm = (w & 1) * 64;
    const int wn = (w >> 1) * WN;

    float c[4][4][4];
#pragma unroll
    for (int mi = 0; mi < 4; mi++)
#pragma unroll
        for (int nj = 0; nj < 4; nj++)
#pragma unroll
            for (int q = 0; q < 4; q++) c[mi][nj][q] = 0.f;

    const int lr = lane & 15;
    const int lc = (lane >> 4) << 3;

#pragma unroll
    for (int kk = 0; kk < 8; kk++) {
        const int k0 = kk * 16;
        uint32_t a[4][4];
#pragma unroll
        for (int mi = 0; mi < 4; mi++) {
            uint32_t addr = s2u(As + (wm + mi * 16 + lr) * LDA + k0 + lc);
            ldsm_x4(a[mi][0], a[mi][1], a[mi][2], a[mi][3], addr);
        }
        uint32_t b[4][2];
#pragma unroll
        for (int bj = 0; bj < NF / 2; bj++) {
            uint32_t r0, r1, r2, r3;
            uint32_t addr = s2u(Bs + (k0 + lr) * LDB + wn + bj * 16 + lc);
            ldsm_x4_t(r0, r1, r2, r3, addr);
            b[bj * 2][0] = r0;     b[bj * 2][1] = r1;
            b[bj * 2 + 1][0] = r2; b[bj * 2 + 1][1] = r3;
        }
#pragma unroll
        for (int mi = 0; mi < 4; mi++)
#pragma unroll
            for (int nj = 0; nj < NF; nj++)
                mma_16816(c[mi][nj], a[mi], b[nj]);
    }

    // epilogue: convert fp16, store (no scaling)
    const int qr = lane >> 2;
    const int qc = (lane & 3) * 2;
#pragma unroll
    for (int mi = 0; mi < 4; mi++) {
        int r0 = m0 + wm + mi * 16 + qr;
        int r1 = r0 + 8;
#pragma unroll
        for (int nj = 0; nj < NF; nj++) {
            int col = wn + nj * 8 + qc;
            if (r0 < N_NODES) {
                __half2 h = __floats2half2_rn(c[mi][nj][0], c[mi][nj][1]);
                *(uint32_t*)(Y + (size_t)r0 * BN + col) = *(uint32_t*)&h;
            }
            if (r1 < N_NODES) {
                __half2 h = __floats2half2_rn(c[mi][nj][2], c[mi][nj][3]);
                *(uint32_t*)(Y + (size_t)r1 * BN + col) = *(uint32_t*)&h;
            }
        }
    }
}

// ---------------- aggregation DIM=128: 2 nodes/warp, 16 lanes x uint4 per node ----------------
// per-edge nsrc scaling: out[d] = relu(ndst[d] * sum_s nsrc[s]*y[s] + b)
__global__ __launch_bounds__(256) void agg128x2_kernel(const __half* __restrict__ y,
                                                       __half* __restrict__ out,
                                                       const float* __restrict__ bias) {
    int gw   = (blockIdx.x * blockDim.x + threadIdx.x) >> 5;
    int lane = threadIdx.x & 31;
    int node = gw * 2 + (lane >> 4);
    int sub  = lane & 15;
    if (node >= N_NODES) return;

    int c = g_cnt[node]; if (c > CAP) c = CAP;
    const int* lst = g_csr + (size_t)node * CAP;
    const uint4* y4 = (const uint4*)y;

    float acc[8];
#pragma unroll
    for (int q = 0; q < 8; q++) acc[q] = 0.f;

#pragma unroll 4
    for (int i = 0; i < c; i++) {
        int s = lst[i];
        float ns = g_nsrc[s];
        uint4 v = y4[(size_t)s * 16 + sub];
        float2 f0 = __half22float2(*(const __half2*)&v.x);
        float2 f1 = __half22float2(*(const __half2*)&v.y);
        float2 f2 = __half22float2(*(const __half2*)&v.z);
        float2 f3 = __half22float2(*(const __half2*)&v.w);
        acc[0] = fmaf(f0.x, ns, acc[0]); acc[1] = fmaf(f0.y, ns, acc[1]);
        acc[2] = fmaf(f1.x, ns, acc[2]); acc[3] = fmaf(f1.y, ns, acc[3]);
        acc[4] = fmaf(f2.x, ns, acc[4]); acc[5] = fmaf(f2.y, ns, acc[5]);
        acc[6] = fmaf(f3.x, ns, acc[6]); acc[7] = fmaf(f3.y, ns, acc[7]);
    }

    float nd = g_ndst[node];
    float4 b0 = ((const float4*)bias)[sub * 2];
    float4 b1 = ((const float4*)bias)[sub * 2 + 1];
    float r0 = fmaxf(fmaf(acc[0], nd, b0.x), 0.f);
    float r1 = fmaxf(fmaf(acc[1], nd, b0.y), 0.f);
    float r2 = fmaxf(fmaf(acc[2], nd, b0.z), 0.f);
    float r3 = fmaxf(fmaf(acc[3], nd, b0.w), 0.f);
    float r4 = fmaxf(fmaf(acc[4], nd, b1.x), 0.f);
    float r5 = fmaxf(fmaf(acc[5], nd, b1.y), 0.f);
    float r6 = fmaxf(fmaf(acc[6], nd, b1.z), 0.f);
    float r7 = fmaxf(fmaf(acc[7], nd, b1.w), 0.f);

    __half2 h0 = __floats2half2_rn(r0, r1);
    __half2 h1 = __floats2half2_rn(r2, r3);
    __half2 h2 = __floats2half2_rn(r4, r5);
    __half2 h3 = __floats2half2_rn(r6, r7);
    uint4 o;
    o.x = *(uint32_t*)&h0; o.y = *(uint32_t*)&h1;
    o.z = *(uint32_t*)&h2; o.w = *(uint32_t*)&h3;
    ((uint4*)out)[(size_t)node * 16 + sub] = o;
}

// ---------------- aggregation DIM=64 + log_softmax: 4 nodes/warp, 8 lanes x uint4 ----------------
__global__ __launch_bounds__(256) void agg64x4_lsm_kernel(const __half* __restrict__ y,
                                                          float* __restrict__ out,
                                                          const float* __restrict__ bias) {
    int gw   = (blockIdx.x * blockDim.x + threadIdx.x) >> 5;
    int lane = threadIdx.x & 31;
    int node = gw * 4 + (lane >> 3);
    int sub  = lane & 7;
    if (node >= N_NODES) return;

    int c = g_cnt[node]; if (c > CAP) c = CAP;
    const int* lst = g_csr + (size_t)node * CAP;
    const uint4* y4 = (const uint4*)y;

    float acc[8];
#pragma unroll
    for (int q = 0; q < 8; q++) acc[q] = 0.f;

#pragma unroll 4
    for (int i = 0; i < c; i++) {
        int s = lst[i];
        float ns = g_nsrc[s];
        uint4 v = y4[(size_t)s * 8 + sub];
        float2 f0 = __half22float2(*(const __half2*)&v.x);
        float2 f1 = __half22float2(*(const __half2*)&v.y);
        float2 f2 = __half22float2(*(const __half2*)&v.z);
        float2 f3 = __half22float2(*(const __half2*)&v.w);
        acc[0] = fmaf(f0.x, ns, acc[0]); acc[1] = fmaf(f0.y, ns, acc[1]);
        acc[2] = fmaf(f1.x, ns, acc[2]); acc[3] = fmaf(f1.y, ns, acc[3]);
        acc[4] = fmaf(f2.x, ns, acc[4]); acc[5] = fmaf(f2.y, ns, acc[5]);
        acc[6] = fmaf(f3.x, ns, acc[6]); acc[7] = fmaf(f3.y, ns, acc[7]);
    }

    float nd = g_ndst[node];
    float4 b0 = ((const float4*)bias)[sub * 2];
    float4 b1 = ((const float4*)bias)[sub * 2 + 1];
    float v[8];
    v[0] = fmaxf(fmaf(acc[0], nd, b0.x), 0.f);
    v[1] = fmaxf(fmaf(acc[1], nd, b0.y), 0.f);
    v[2] = fmaxf(fmaf(acc[2], nd, b0.z), 0.f);
    v[3] = fmaxf(fmaf(acc[3], nd, b0.w), 0.f);
    v[4] = fmaxf(fmaf(acc[4], nd, b1.x), 0.f);
    v[5] = fmaxf(fmaf(acc[5], nd, b1.y), 0.f);
    v[6] = fmaxf(fmaf(acc[6], nd, b1.z), 0.f);
    v[7] = fmaxf(fmaf(acc[7], nd, b1.w), 0.f);

    float m = v[0];
#pragma unroll
    for (int q = 1; q < 8; q++) m = fmaxf(m, v[q]);
#pragma unroll
    for (int off = 4; off > 0; off >>= 1)
        m = fmaxf(m, __shfl_xor_sync(0xffffffffu, m, off));
    float s = 0.f;
#pragma unroll
    for (int q = 0; q < 8; q++) s += expf(v[q] - m);
#pragma unroll
    for (int off = 4; off > 0; off >>= 1)
        s += __shfl_xor_sync(0xffffffffu, s, off);
    float l = m + logf(s);

    float4 o0 = make_float4(v[0] - l, v[1] - l, v[2] - l, v[3] - l);
    float4 o1 = make_float4(v[4] - l, v[5] - l, v[6] - l, v[7] - l);
    float4* op = (float4*)(out + (size_t)node * 64 + sub * 8);
    op[0] = o0;
    op[1] = o1;
}

// ---------------- launch ----------------
extern "C" void kernel_launch(void* const* d_in, const int* in_sizes, int n_in,
                              void* d_out, int out_size) {
    const float* feats = (const float*)d_in[0];
    const float* W0 = (const float*)d_in[1];
    const float* b0 = (const float*)d_in[2];
    const float* W1 = (const float*)d_in[3];
    const float* b1 = (const float*)d_in[4];
    const float* W2 = (const float*)d_in[5];
    const float* b2 = (const float*)d_in[6];
    const int*  src = (const int*)d_in[7];
    const int*  dst = (const int*)d_in[8];
    float* out = (float*)d_out;

    __half* y16; cudaGetSymbolAddress((void**)&y16, g_y16);
    __half* h16; cudaGetSymbolAddress((void**)&h16, g_h16);
    __half* w0h; cudaGetSymbolAddress((void**)&w0h, g_w0h);
    __half* w1h; cudaGetSymbolAddress((void**)&w1h, g_w1h);
    __half* w2h; cudaGetSymbolAddress((void**)&w2h, g_w2h);

    const int NT = 256;
    int nodeBlocks = (N_NODES + NT - 1) / NT;
    int edgeBlocks = (N_EDGES + NT - 1) / NT;
    int gemmBlocks = (N_NODES + 127) / 128;
    int agg128Blocks = ((N_NODES + 1) / 2 * 32 + NT - 1) / NT;
    int agg64Blocks  = ((N_NODES + 3) / 4 * 32 + NT - 1) / NT;

    const int SMEM128 = (128 * 136 + 128 * 136) * 2;   // 69632
    const int SMEM64  = (128 * 136 + 128 * 72) * 2;    // 53248
    cudaFuncSetAttribute(hgemm_kernel<128, true>,  cudaFuncAttributeMaxDynamicSharedMemorySize, SMEM128);
    cudaFuncSetAttribute(hgemm_kernel<128, false>, cudaFuncAttributeMaxDynamicSharedMemorySize, SMEM128);
    cudaFuncSetAttribute(hgemm_kernel<64, false>,  cudaFuncAttributeMaxDynamicSharedMemorySize, SMEM64);

    // Two independent front chains, forked/joined with events so the
    // captured graph runs them concurrently:
    //   branch A (capture stream): cvtw -> gemm1         (dense math)
    //   branch B (side stream):    zero -> build -> norm (graph structure)
    cudaStream_t sB;
    cudaStreamCreateWithFlags(&sB, cudaStreamNonBlocking);
    cudaEvent_t eFork, eJoin;
    cudaEventCreateWithFlags(&eFork, cudaEventDisableTiming);
    cudaEventCreateWithFlags(&eJoin, cudaEventDisableTiming);

    cudaEventRecord(eFork, 0);
    cudaStreamWaitEvent(sB, eFork, 0);

    zero_kernel<<<nodeBlocks, NT, 0, sB>>>();
    build_kernel<<<edgeBlocks, NT, 0, sB>>>(src, dst);
    norm_kernel<<<nodeBlocks, NT, 0, sB>>>();
    cudaEventRecord(eJoin, sB);

    cvtw_kernel<<<40, NT>>>(W0, W1, W2, w0h, w1h, w2h);
    hgemm_kernel<128, true><<<gemmBlocks, NT, SMEM128>>>(feats, (const __half*)0, w0h, y16);

    cudaStreamWaitEvent(0, eJoin, 0);

    agg128x2_kernel<<<agg128Blocks, NT>>>(y16, h16, b0);

    hgemm_kernel<128, false><<<gemmBlocks, NT, SMEM128>>>((const float*)0, h16, w1h, y16);
    agg128x2_kernel<<<agg128Blocks, NT>>>(y16, h16, b1);

    hgemm_kernel<64, false><<<gemmBlocks, NT, SMEM64>>>((const float*)0, h16, w2h, y16);
    agg64x4_lsm_kernel<<<agg64Blocks, NT>>>(y16, out, b2);

    cudaEventDestroy(eFork);
    cudaEventDestroy(eJoin);
    cudaStreamDestroy(sB);
}